// round 4
// baseline (speedup 1.0000x reference)
#include <cuda_runtime.h>

// EdgesToGlobalsAggregator: segment-sum of edges [TOTAL_EDGES, 128] fp32 into
// [num_graphs, 128] fp32. Split-K: each graph's segment is processed by SPLIT
// blocks (finer work quantum -> smaller straggler tail), partials reduced by a
// tiny second kernel.

#define D_FEAT 128
#define VEC (D_FEAT / 4)   // 32 float4 per row
#define NTHREADS 256
#define SPLIT 4
#define MAX_GRAPHS 1024

// 1024 graphs * 4 splits * 32 float4 = 2 MB scratch
__device__ float4 g_partials[MAX_GRAPHS * SPLIT * VEC];

__global__ __launch_bounds__(NTHREADS, 4)
void segment_partial_kernel(const float4* __restrict__ edges,
                            const int* __restrict__ n_edge,
                            float4* __restrict__ partials) {
    const int g     = blockIdx.x >> 2;      // graph id
    const int chunk = blockIdx.x & (SPLIT - 1);
    const int tid   = threadIdx.x;
    const int lane  = tid & 31;             // float4 feature slot 0..31
    const int warp  = tid >> 5;             // row-slice 0..7

    // ---- per-block exclusive prefix: start = sum(n_edge[0..g-1])
    __shared__ int s_warp[8];
    __shared__ int s_start, s_mine;

    int local = 0;
    for (int i = tid; i < g; i += NTHREADS)
        local += __ldg(&n_edge[i]);
    #pragma unroll
    for (int off = 16; off > 0; off >>= 1)
        local += __shfl_down_sync(0xFFFFFFFFu, local, off);
    if (lane == 0) s_warp[warp] = local;
    __syncthreads();
    if (tid == 0) {
        int acc = 0;
        #pragma unroll
        for (int i = 0; i < 8; i++) acc += s_warp[i];
        s_start = acc;
        s_mine  = __ldg(&n_edge[g]);
    }
    __syncthreads();

    const int seg_start = s_start;
    const int seg_rows  = s_mine;

    // this block's sub-range of the segment
    const int c_begin = (int)(((long long)seg_rows * chunk) / SPLIT);
    const int c_end   = (int)(((long long)seg_rows * (chunk + 1)) / SPLIT);
    const int nrows   = c_end - c_begin;

    const float4* __restrict__ base = edges + (size_t)(seg_start + c_begin) * VEC;

    float4 a0 = make_float4(0.f, 0.f, 0.f, 0.f);
    float4 a1 = make_float4(0.f, 0.f, 0.f, 0.f);
    float4 a2 = make_float4(0.f, 0.f, 0.f, 0.f);
    float4 a3 = make_float4(0.f, 0.f, 0.f, 0.f);

    int r = warp;
    // 4-way unrolled main loop: 4 independent streaming LDG.128 in flight.
    for (; r + 24 < nrows; r += 32) {
        float4 v0 = __ldcs(&base[(size_t)(r)      * VEC + lane]);
        float4 v1 = __ldcs(&base[(size_t)(r + 8)  * VEC + lane]);
        float4 v2 = __ldcs(&base[(size_t)(r + 16) * VEC + lane]);
        float4 v3 = __ldcs(&base[(size_t)(r + 24) * VEC + lane]);
        a0.x += v0.x; a0.y += v0.y; a0.z += v0.z; a0.w += v0.w;
        a1.x += v1.x; a1.y += v1.y; a1.z += v1.z; a1.w += v1.w;
        a2.x += v2.x; a2.y += v2.y; a2.z += v2.z; a2.w += v2.w;
        a3.x += v3.x; a3.y += v3.y; a3.z += v3.z; a3.w += v3.w;
    }
    // tail
    for (; r < nrows; r += 8) {
        float4 v = __ldcs(&base[(size_t)r * VEC + lane]);
        a0.x += v.x; a0.y += v.y; a0.z += v.z; a0.w += v.w;
    }

    a0.x += a1.x + a2.x + a3.x;
    a0.y += a1.y + a2.y + a3.y;
    a0.z += a1.z + a2.z + a3.z;
    a0.w += a1.w + a2.w + a3.w;

    __shared__ float4 sp[8][32];
    sp[warp][lane] = a0;
    __syncthreads();

    if (warp == 0) {
        float4 s = sp[0][lane];
        #pragma unroll
        for (int i = 1; i < 8; i++) {
            float4 v = sp[i][lane];
            s.x += v.x; s.y += v.y; s.z += v.z; s.w += v.w;
        }
        partials[(size_t)blockIdx.x * VEC + lane] = s;
    }
}

__global__ __launch_bounds__(32, 16)
void combine_kernel(const float4* __restrict__ partials,
                    float4* __restrict__ out) {
    const int g    = blockIdx.x;
    const int lane = threadIdx.x;  // 0..31

    float4 s = partials[(size_t)(g * SPLIT) * VEC + lane];
    #pragma unroll
    for (int i = 1; i < SPLIT; i++) {
        float4 v = partials[(size_t)(g * SPLIT + i) * VEC + lane];
        s.x += v.x; s.y += v.y; s.z += v.z; s.w += v.w;
    }
    out[(size_t)g * VEC + lane] = s;
}

extern "C" void kernel_launch(void* const* d_in, const int* in_sizes, int n_in,
                              void* d_out, int out_size) {
    const float* edges  = (const float*)d_in[0];
    const int*   n_edge = (const int*)d_in[1];
    const int num_graphs = in_sizes[1];          // 1024

    float4* partials = nullptr;
    cudaGetSymbolAddress((void**)&partials, g_partials);

    segment_partial_kernel<<<num_graphs * SPLIT, NTHREADS>>>(
        (const float4*)edges, n_edge, partials);
    combine_kernel<<<num_graphs, 32>>>(partials, (float4*)d_out);
}

// round 5
// speedup vs baseline: 1.0246x; 1.0246x over previous
#include <cuda_runtime.h>

// EdgesToGlobalsAggregator: segment-sum of edges [TOTAL_EDGES, 128] fp32 into
// [num_graphs, 128] fp32.
// Flat partition: grid = 608 CTAs (4 per SM on 152-SM GB300), each CTA owns an
// identical contiguous row window of the flat edge stream (perfect per-SM byte
// balance, single wave). Windows cross graph boundaries; per-graph partials are
// folded into the (pre-zeroed) output with atomicAdd. Each block builds the
// n_edge prefix in SMEM itself (4 KB, L2-hot).

#define D_FEAT 128
#define VEC (D_FEAT / 4)     // 32 float4 per row
#define NTHREADS 256
#define MAX_GRAPHS 1024
#define GRID 608             // 152 SMs * 4 CTAs

__global__ __launch_bounds__(512)
void zero_out_kernel(float4* __restrict__ out, int n4) {
    int i = blockIdx.x * 512 + threadIdx.x;
    if (i < n4) out[i] = make_float4(0.f, 0.f, 0.f, 0.f);
}

__global__ __launch_bounds__(NTHREADS, 4)
void flat_segment_kernel(const float4* __restrict__ edges,
                         const int* __restrict__ n_edge,
                         int num_graphs,
                         float* __restrict__ out) {
    __shared__ int offs[MAX_GRAPHS + 1];   // exclusive prefix, offs[num_graphs]=total
    __shared__ int warp_sums[8];
    __shared__ float4 sp[8][32];

    const int tid  = threadIdx.x;
    const int lane = tid & 31;
    const int warp = tid >> 5;

    // ---- block-local exclusive scan of n_edge (thread owns 4 consecutive) ----
    int v0_, v1_, v2_, v3_;
    {
        int i0 = 4 * tid;
        v0_ = (i0 + 0 < num_graphs) ? __ldg(&n_edge[i0 + 0]) : 0;
        v1_ = (i0 + 1 < num_graphs) ? __ldg(&n_edge[i0 + 1]) : 0;
        v2_ = (i0 + 2 < num_graphs) ? __ldg(&n_edge[i0 + 2]) : 0;
        v3_ = (i0 + 3 < num_graphs) ? __ldg(&n_edge[i0 + 3]) : 0;
    }
    int loc = v0_ + v1_ + v2_ + v3_;
    int sc = loc;
    #pragma unroll
    for (int off = 1; off < 32; off <<= 1) {
        int n = __shfl_up_sync(0xFFFFFFFFu, sc, off);
        if (lane >= off) sc += n;
    }
    if (lane == 31) warp_sums[warp] = sc;
    __syncthreads();
    int wbase = 0;
    #pragma unroll
    for (int i = 0; i < 8; i++) if (i < warp) wbase += warp_sums[i];
    int run = wbase + sc - loc;      // exclusive prefix of this thread's chunk
    {
        int i0 = 4 * tid;
        offs[i0 + 0] = run;  run += v0_;
        offs[i0 + 1] = run;  run += v1_;
        offs[i0 + 2] = run;  run += v2_;
        offs[i0 + 3] = run;  run += v3_;
        if (tid == NTHREADS - 1) offs[4 * NTHREADS] = run;  // total
    }
    __syncthreads();

    const int total = offs[num_graphs];

    // ---- this CTA's flat row window [r0, r1) ----
    const long long t = total;
    int r = (int)((t * blockIdx.x) / gridDim.x);
    const int r1 = (int)((t * (blockIdx.x + 1)) / gridDim.x);

    // binary search: largest g with offs[g] <= r
    int gcur;
    {
        int lo = 0, hi = num_graphs;
        while (lo < hi) {
            int mid = (lo + hi + 1) >> 1;
            if (offs[mid] <= r) lo = mid; else hi = mid - 1;
        }
        gcur = lo;
    }

    while (r < r1) {
        while (offs[gcur + 1] <= r) gcur++;           // skip empty graphs
        const int e = min(offs[gcur + 1], r1);
        const int nrows = e - r;
        const float4* __restrict__ base = edges + (size_t)r * VEC;

        float4 a0 = make_float4(0.f, 0.f, 0.f, 0.f);
        float4 a1 = make_float4(0.f, 0.f, 0.f, 0.f);
        float4 a2 = make_float4(0.f, 0.f, 0.f, 0.f);
        float4 a3 = make_float4(0.f, 0.f, 0.f, 0.f);

        int row = warp;
        for (; row + 24 < nrows; row += 32) {
            float4 x0 = __ldcs(&base[(size_t)(row)      * VEC + lane]);
            float4 x1 = __ldcs(&base[(size_t)(row + 8)  * VEC + lane]);
            float4 x2 = __ldcs(&base[(size_t)(row + 16) * VEC + lane]);
            float4 x3 = __ldcs(&base[(size_t)(row + 24) * VEC + lane]);
            a0.x += x0.x; a0.y += x0.y; a0.z += x0.z; a0.w += x0.w;
            a1.x += x1.x; a1.y += x1.y; a1.z += x1.z; a1.w += x1.w;
            a2.x += x2.x; a2.y += x2.y; a2.z += x2.z; a2.w += x2.w;
            a3.x += x3.x; a3.y += x3.y; a3.z += x3.z; a3.w += x3.w;
        }
        for (; row < nrows; row += 8) {
            float4 x = __ldcs(&base[(size_t)row * VEC + lane]);
            a0.x += x.x; a0.y += x.y; a0.z += x.z; a0.w += x.w;
        }

        a0.x += a1.x + a2.x + a3.x;
        a0.y += a1.y + a2.y + a3.y;
        a0.z += a1.z + a2.z + a3.z;
        a0.w += a1.w + a2.w + a3.w;

        sp[warp][lane] = a0;
        __syncthreads();

        if (warp == 0) {
            float4 s = sp[0][lane];
            #pragma unroll
            for (int i = 1; i < 8; i++) {
                float4 v = sp[i][lane];
                s.x += v.x; s.y += v.y; s.z += v.z; s.w += v.w;
            }
            float* dst = out + (size_t)gcur * D_FEAT + lane * 4;
            atomicAdd(dst + 0, s.x);
            atomicAdd(dst + 1, s.y);
            atomicAdd(dst + 2, s.z);
            atomicAdd(dst + 3, s.w);
        }
        __syncthreads();   // sp reuse + uniform loop step
        r = e;
    }
}

extern "C" void kernel_launch(void* const* d_in, const int* in_sizes, int n_in,
                              void* d_out, int out_size) {
    const float* edges  = (const float*)d_in[0];
    const int*   n_edge = (const int*)d_in[1];
    const int num_graphs = in_sizes[1];          // 1024

    const int n4 = out_size / 4;                 // float4 count of output
    zero_out_kernel<<<(n4 + 511) / 512, 512>>>((float4*)d_out, n4);
    flat_segment_kernel<<<GRID, NTHREADS>>>(
        (const float4*)edges, n_edge, num_graphs, (float*)d_out);
}

// round 6
// speedup vs baseline: 1.0548x; 1.0295x over previous
#include <cuda_runtime.h>

// EdgesToGlobalsAggregator: segment-sum of edges [TOTAL_EDGES, 128] fp32 into
// [num_graphs, 128] fp32. Fused single kernel: each block computes its own
// exclusive prefix of n_edge (4KB, L2-resident), then streams its segment.
// R6: identical to R2 except default-policy loads (no __ldcs) — evict-first
// streaming policy measured 1.7pp lower DRAM busy on this pure-stream kernel.

#define D_FEAT 128
#define VEC (D_FEAT / 4)   // 32 float4 per row
#define NTHREADS 256

__global__ __launch_bounds__(NTHREADS, 4)
void segment_sum_fused_kernel(const float4* __restrict__ edges,
                              const int* __restrict__ n_edge,
                              int num_graphs,
                              float4* __restrict__ out) {
    const int g    = blockIdx.x;
    const int tid  = threadIdx.x;
    const int lane = tid & 31;   // float4 feature slot 0..31
    const int warp = tid >> 5;   // row-slice 0..7

    // ---- per-block exclusive prefix: start = sum(n_edge[0..g-1]), mine = n_edge[g]
    __shared__ int s_warp[8];
    __shared__ int s_start, s_mine;

    int local = 0;
    for (int i = tid; i < g; i += NTHREADS)
        local += __ldg(&n_edge[i]);
    #pragma unroll
    for (int off = 16; off > 0; off >>= 1)
        local += __shfl_down_sync(0xFFFFFFFFu, local, off);
    if (lane == 0) s_warp[warp] = local;
    __syncthreads();
    if (tid == 0) {
        int acc = 0;
        #pragma unroll
        for (int i = 0; i < 8; i++) acc += s_warp[i];
        s_start = acc;
        s_mine  = __ldg(&n_edge[g]);
    }
    __syncthreads();

    const int start = s_start;
    const int nrows = s_mine;

    const float4* __restrict__ base = edges + (size_t)start * VEC;

    float4 a0 = make_float4(0.f, 0.f, 0.f, 0.f);
    float4 a1 = make_float4(0.f, 0.f, 0.f, 0.f);
    float4 a2 = make_float4(0.f, 0.f, 0.f, 0.f);
    float4 a3 = make_float4(0.f, 0.f, 0.f, 0.f);

    int r = warp;
    // 4-way unrolled main loop: 4 independent LDG.128 in flight per iter.
    for (; r + 24 < nrows; r += 32) {
        float4 v0 = base[(size_t)(r)      * VEC + lane];
        float4 v1 = base[(size_t)(r + 8)  * VEC + lane];
        float4 v2 = base[(size_t)(r + 16) * VEC + lane];
        float4 v3 = base[(size_t)(r + 24) * VEC + lane];
        a0.x += v0.x; a0.y += v0.y; a0.z += v0.z; a0.w += v0.w;
        a1.x += v1.x; a1.y += v1.y; a1.z += v1.z; a1.w += v1.w;
        a2.x += v2.x; a2.y += v2.y; a2.z += v2.z; a2.w += v2.w;
        a3.x += v3.x; a3.y += v3.y; a3.z += v3.z; a3.w += v3.w;
    }
    // tail
    for (; r < nrows; r += 8) {
        float4 v = base[(size_t)r * VEC + lane];
        a0.x += v.x; a0.y += v.y; a0.z += v.z; a0.w += v.w;
    }

    a0.x += a1.x + a2.x + a3.x;
    a0.y += a1.y + a2.y + a3.y;
    a0.z += a1.z + a2.z + a3.z;
    a0.w += a1.w + a2.w + a3.w;

    __shared__ float4 sp[8][32];
    sp[warp][lane] = a0;
    __syncthreads();

    if (warp == 0) {
        float4 s = sp[0][lane];
        #pragma unroll
        for (int i = 1; i < 8; i++) {
            float4 v = sp[i][lane];
            s.x += v.x; s.y += v.y; s.z += v.z; s.w += v.w;
        }
        out[(size_t)g * VEC + lane] = s;
    }
}

extern "C" void kernel_launch(void* const* d_in, const int* in_sizes, int n_in,
                              void* d_out, int out_size) {
    const float* edges  = (const float*)d_in[0];
    const int*   n_edge = (const int*)d_in[1];
    const int num_graphs = in_sizes[1];          // 1024

    segment_sum_fused_kernel<<<num_graphs, NTHREADS>>>(
        (const float4*)edges, n_edge, num_graphs, (float4*)d_out);
}